// round 13
// baseline (speedup 1.0000x reference)
#include <cuda_runtime.h>
#include <cstdint>
#include <cstddef>

// Problem shapes (fixed per metadata)
#define B_ 8
#define K_ 1024
#define L_ 1024
#define D_ 1024
#define O_ 6
#define E_ 128
#define KS_ 16            // k-split for u-sum partials
#define KT_ 16            // k tile per block in the fused pass
#define NBLK_K (K_/KT_)   // 64 k-tiles
#define DSP_ 256          // d-splits per o in k_v_part
#define DPB_ (D_/DSP_)    // 4 d per block

// ---------------- scratch (device globals; no allocation allowed) ----------------
__device__ __align__(16) float g_us_part[B_*KS_*D_];
__device__ __align__(16) float g_w[B_*O_*D_];          // w[b,o,d] = sum_e W[o,d,e]*v[b,o,e]
__device__ __align__(16) float g_logits[B_*K_*O_];     // logits after iteration-2
__device__ __align__(16) float g_t_part[(size_t)B_*NBLK_K*O_*D_];   // 12.6MB
__device__ __align__(16) float g_vpart[O_][DSP_][B_][E_];           // 6.3MB
__device__ __align__(16) float g_v[B_*O_*E_];          // current squashed v
__device__ unsigned char g_mask[B_*K_];

// ---------------- u-sum over k (deterministic split-K) + fused mask ingest ------
__global__ void k_usum_part(const float* __restrict__ u, const void* __restrict__ raw) {
    int tid = threadIdx.x;                    // 256
    int d = blockIdx.x * 256 + tid;
    int ks = blockIdx.y;
    int b = blockIdx.z;
    // fused mask ingest: 8 blocks (x==0, ks==0), one per b, each handles its slice.
    if (blockIdx.x == 0 && ks == 0) {
        __shared__ int flag;
        if (tid == 0) flag = 0;
        __syncthreads();
        const unsigned int* w32 = (const unsigned int*)raw;
        int f = 0;
        for (int i = tid; i < (B_*K_)/4; i += 256)
            if (w32[i] > 1u) f = 1;          // packed bytes => value like 0x00010001
        if (f) atomicOr(&flag, 1);
        __syncthreads();
        int isbyte = flag;
        const unsigned char* b8 = (const unsigned char*)raw;
        for (int i = tid; i < K_; i += 256) {
            int idx = b*K_ + i;
            unsigned char m = isbyte ? b8[idx] : (unsigned char)(w32[idx] != 0u);
            g_mask[idx] = m ? (unsigned char)1 : (unsigned char)0;
        }
    }
    int k0 = ks * (K_/KS_);
    const float* up = u + ((size_t)b*K_ + k0)*D_ + d;
    float s = 0.f;
    #pragma unroll 8
    for (int k = 0; k < K_/KS_; ++k) s += up[(size_t)k*D_];
    g_us_part[((size_t)b*KS_ + ks)*D_ + d] = s;
}

// ---------------- v partials (t-reduction fused, 4-thread-split) ----------------
// vpart[o,dblk,b,e] = sum_{d in blk} t[b,o,d]*W[o,d,e]
// t[b,o,d] = sum over NBLK_K g_t_part (use_t=1) or sum over KS_ g_us_part (use_t=0).
__global__ void __launch_bounds__(128) k_v_part(int use_t, const float* __restrict__ W) {
    int o = blockIdx.y;
    int dblk = blockIdx.x;            // [0, DSP_)
    int d0 = dblk * DPB_;
    int tid = threadIdx.x;            // 128
    __shared__ float red[B_*DPB_][4];
    __shared__ float st[B_][DPB_];
    {
        int entry = tid >> 2;         // 0..31 = b*DPB_+dd
        int sub = tid & 3;
        int b = entry / DPB_, dd = entry % DPB_;
        float s = 0.f;
        if (use_t) {
            const float* p = g_t_part + ((size_t)b*NBLK_K*O_ + o)*D_ + d0 + dd;
            #pragma unroll 16
            for (int j = sub; j < NBLK_K; j += 4) s += p[(size_t)j*O_*D_];
        } else {
            const float* p = g_us_part + (size_t)b*KS_*D_ + d0 + dd;
            #pragma unroll 4
            for (int j = sub; j < KS_; j += 4) s += p[(size_t)j*D_];
        }
        red[entry][sub] = s;
    }
    __syncthreads();
    if (tid < B_*DPB_) {
        int b = tid / DPB_, dd = tid % DPB_;
        st[b][dd] = red[tid][0] + red[tid][1] + red[tid][2] + red[tid][3];
    }
    __syncthreads();
    int e = tid;
    const float* Wo = W + ((size_t)o*D_ + d0)*E_ + e;
    float acc[B_];
    #pragma unroll
    for (int b = 0; b < B_; ++b) acc[b] = 0.f;
    #pragma unroll
    for (int dd = 0; dd < DPB_; ++dd) {
        float wv = Wo[(size_t)dd*E_];
        #pragma unroll
        for (int b = 0; b < B_; ++b) acc[b] += wv * st[b][dd];
    }
    #pragma unroll
    for (int b = 0; b < B_; ++b) g_vpart[o][dblk][b][e] = acc[b];
}

// ---------------- combine partials + squash -> g_v (512 thr, 4-way e-split) -----
__global__ void __launch_bounds__(512) k_v_comb(float scale) {
    int bo = blockIdx.x;              // [0, B*O)
    int b = bo / O_;
    int o = bo % O_;
    int tid = threadIdx.x;            // 512
    int e = tid & (E_-1);
    int q = tid >> 7;                 // 0..3
    float v = 0.f;
    #pragma unroll 16
    for (int s = q; s < DSP_; s += 4) v += g_vpart[o][s][b][e];
    __shared__ float part[4][E_];
    __shared__ float sv[E_];
    __shared__ float ssq;
    part[q][e] = v;
    __syncthreads();
    if (q == 0) {
        v = (part[0][e] + part[1][e] + part[2][e] + part[3][e]) * scale;
        sv[e] = v;
    }
    __syncthreads();
    if (tid < 32) {
        float s2 = sv[tid]*sv[tid] + sv[tid+32]*sv[tid+32]
                 + sv[tid+64]*sv[tid+64] + sv[tid+96]*sv[tid+96];
        #pragma unroll
        for (int off = 16; off; off >>= 1) s2 += __shfl_xor_sync(0xffffffffu, s2, off);
        if (tid == 0) ssq = s2;
    }
    __syncthreads();
    if (q == 0) {
        float sq = ssq;
        float factor = sq / (1.f + sq) / (sqrtf(sq) + 1e-8f);
        g_v[(size_t)bo*E_ + e] = sv[e] * factor;
    }
}

// ---------------- w[b,o,d] = sum_e W[o,d,e] * v[b,o,e] ----------------
__global__ void __launch_bounds__(256) k_w(const float* __restrict__ W) {
    int o = blockIdx.y;
    int d = blockIdx.x * 8 + (threadIdx.x >> 5);
    int lane = threadIdx.x & 31;
    __shared__ float sv[B_][E_];
    for (int i = threadIdx.x; i < B_*E_; i += 256) {
        int b = i >> 7; int e = i & (E_-1);
        sv[b][e] = g_v[((size_t)b*O_ + o)*E_ + e];
    }
    __syncthreads();
    const float* Wr = W + ((size_t)o*D_ + d)*E_;
    float a[B_];
    #pragma unroll
    for (int b = 0; b < B_; ++b) a[b] = 0.f;
    #pragma unroll
    for (int j = 0; j < E_/32; ++j) {
        int e = j*32 + lane;
        float wv = Wr[e];
        #pragma unroll
        for (int b = 0; b < B_; ++b) a[b] += wv * sv[b][e];
    }
    #pragma unroll
    for (int b = 0; b < B_; ++b) {
        #pragma unroll
        for (int off = 16; off; off >>= 1)
            a[b] += __shfl_xor_sync(0xffffffffu, a[b], off);
    }
    if (lane == 0) {
        #pragma unroll
        for (int b = 0; b < B_; ++b)
            g_w[((size_t)b*O_ + o)*D_ + d] = a[b];
    }
}

// ---------------- fused routing pass (KT=16, 512 blocks) ----------------
// iter3==0: logits2 -> g_logits.  iter3==1: probs3 broadcast directly to outp.
__global__ void k_pass(const float* __restrict__ u, int iter3,
                       float4* __restrict__ outp) {
    __shared__ float sh_w[O_*D_];                 // 24KB
    __shared__ __align__(16) float sh_p[KT_][O_]; // 96 floats = 24 float4
    int b = blockIdx.y;
    int kblk = blockIdx.x;
    int k0 = kblk * KT_;
    int tid = threadIdx.x;            // 256
    const float* wb = g_w + (size_t)b*O_*D_;
    for (int i = tid; i < O_*D_; i += 256) sh_w[i] = wb[i];
    __syncthreads();
    int warp = tid >> 5, lane = tid & 31;
    for (int kk = warp; kk < KT_; kk += 8) {
        int k = k0 + kk;
        const float* ur = u + ((size_t)b*K_ + k)*D_;
        float a0=0,a1=0,a2=0,a3=0,a4=0,a5=0;
        #pragma unroll
        for (int j = 0; j < D_/32; ++j) {
            int d = j*32 + lane;
            float uv = ur[d];
            a0 += uv * sh_w[0*D_+d];
            a1 += uv * sh_w[1*D_+d];
            a2 += uv * sh_w[2*D_+d];
            a3 += uv * sh_w[3*D_+d];
            a4 += uv * sh_w[4*D_+d];
            a5 += uv * sh_w[5*D_+d];
        }
        #pragma unroll
        for (int off = 16; off; off >>= 1) {
            a0 += __shfl_xor_sync(0xffffffffu, a0, off);
            a1 += __shfl_xor_sync(0xffffffffu, a1, off);
            a2 += __shfl_xor_sync(0xffffffffu, a2, off);
            a3 += __shfl_xor_sync(0xffffffffu, a3, off);
            a4 += __shfl_xor_sync(0xffffffffu, a4, off);
            a5 += __shfl_xor_sync(0xffffffffu, a5, off);
        }
        int base = (b*K_ + k)*O_;
        if (iter3) {
            a0 += g_logits[base+0]; a1 += g_logits[base+1];
            a2 += g_logits[base+2]; a3 += g_logits[base+3];
            a4 += g_logits[base+4]; a5 += g_logits[base+5];
        } else if (lane < O_) {
            float sv = a0;
            if (lane==1) sv=a1; else if (lane==2) sv=a2; else if (lane==3) sv=a3;
            else if (lane==4) sv=a4; else if (lane==5) sv=a5;
            g_logits[base+lane] = sv;
        }
        float m = fmaxf(fmaxf(fmaxf(a0,a1),fmaxf(a2,a3)),fmaxf(a4,a5));
        float e0=__expf(a0-m), e1=__expf(a1-m), e2=__expf(a2-m),
              e3=__expf(a3-m), e4=__expf(a4-m), e5=__expf(a5-m);
        float s = e0+e1+e2+e3+e4+e5;
        bool msk = (g_mask[b*K_ + k] != 0);
        float inv = msk ? (1.0f/6.0f) : (1.0f/s);
        float p0 = msk?inv:e0*inv, p1 = msk?inv:e1*inv, p2 = msk?inv:e2*inv;
        float p3 = msk?inv:e3*inv, p4 = msk?inv:e4*inv, p5 = msk?inv:e5*inv;
        if (lane < O_) {
            float pv = p0;
            if (lane==1) pv=p1; else if (lane==2) pv=p2; else if (lane==3) pv=p3;
            else if (lane==4) pv=p4; else if (lane==5) pv=p5;
            sh_p[kk][lane] = pv;
        }
    }
    __syncthreads();
    // phase B: partial t[o,d] = sum_{k in tile} p[k,o] * u[b,k,d]
    float* tp = g_t_part + ((size_t)b*NBLK_K + kblk)*O_*D_;
    const float* ub = u + ((size_t)b*K_ + k0)*D_;
    #pragma unroll
    for (int r = 0; r < D_/256; ++r) {
        int d = tid + 256*r;
        float t0=0,t1=0,t2=0,t3=0,t4=0,t5=0;
        #pragma unroll
        for (int kk = 0; kk < KT_; ++kk) {
            float uv = ub[(size_t)kk*D_ + d];   // hot in L1/L2 from phase A
            t0 += uv*sh_p[kk][0]; t1 += uv*sh_p[kk][1]; t2 += uv*sh_p[kk][2];
            t3 += uv*sh_p[kk][3]; t4 += uv*sh_p[kk][4]; t5 += uv*sh_p[kk][5];
        }
        tp[0*D_+d]=t0; tp[1*D_+d]=t1; tp[2*D_+d]=t2;
        tp[3*D_+d]=t3; tp[4*D_+d]=t4; tp[5*D_+d]=t5;
    }
    // phase C (iter3 only): broadcast this tile's probs to all L rows of output.
    if (iter3) {
        const float4* sp4 = (const float4*)&sh_p[0][0];   // 24 float4
        const int NV = KT_*O_/4;                           // 24
        size_t dstbase = (size_t)b*L_*(K_*O_/4) + (size_t)kblk*NV;
        for (int idx = tid; idx < L_*NV; idx += 256) {
            int l = idx / NV;
            int j = idx - l*NV;
            __stcs(outp + dstbase + (size_t)l*(K_*O_/4) + j, sp4[j]);
        }
    }
}

// ---------------- outputs_v broadcast ----------------
__global__ void k_bcast_v(float4* __restrict__ dst) {
    const float4* src = (const float4*)g_v;
    const int per = O_*E_/4;                   // 192
    const int total = B_*L_*per;
    for (int i = blockIdx.x*blockDim.x + threadIdx.x; i < total;
         i += gridDim.x*blockDim.x) {
        int bl = i / per;
        int j = i - bl*per;
        int b = bl >> 10;
        __stcs(dst + i, src[b*per + j]);
    }
}

// ---------------- launch ----------------
extern "C" void kernel_launch(void* const* d_in, const int* in_sizes, int n_in,
                              void* d_out, int out_size) {
    const float* u    = (const float*)d_in[0];   // inputs_u (B,K,D)
    // d_in[1] = context_sequence — unused by the math (shape only)
    const float* W    = (const float*)d_in[2];   // route_weights (O,D,E)
    const void*  mask = d_in[3];                 // inputs_mask (B,K)

    float* out   = (float*)d_out;
    float4* outv = (float4*)out;                                  // outputs_v (B,L,O,E)
    float4* outp = (float4*)(out + (size_t)B_*L_*O_*E_);          // probs_c   (B,L,K,O)

    // u-sum partials + mask ingest (fused)
    k_usum_part<<<dim3(D_/256, KS_, B_), 256>>>(u, mask);

    // iteration 1: v1 = squash((1/6) * usum @ W); w1 = W @ v1
    k_v_part<<<dim3(DSP_, O_), 128>>>(0, W);
    k_v_comb<<<B_*O_, 512>>>(1.0f/6.0f);
    k_w<<<dim3(D_/8, O_), 256>>>(W);

    // iteration 2: logits2 = u.w1 (store), probs2, t2 -> v2 -> w2
    k_pass<<<dim3(NBLK_K, B_), 256>>>(u, 0, outp);
    k_v_part<<<dim3(DSP_, O_), 128>>>(1, W);
    k_v_comb<<<B_*O_, 512>>>(1.0f);
    k_w<<<dim3(D_/8, O_), 256>>>(W);

    // iteration 3: logits3 = logits2 + u.w2, probs3 broadcast to outp, t3 -> v3
    k_pass<<<dim3(NBLK_K, B_), 256>>>(u, 1, outp);
    k_v_part<<<dim3(DSP_, O_), 128>>>(1, W);
    k_v_comb<<<B_*O_, 512>>>(1.0f);

    // broadcast outputs_v over L
    k_bcast_v<<<1024, 256>>>(outv);
}

// round 15
// speedup vs baseline: 1.0615x; 1.0615x over previous
#include <cuda_runtime.h>
#include <cstdint>
#include <cstddef>

// Problem shapes (fixed per metadata)
#define B_ 8
#define K_ 1024
#define L_ 1024
#define D_ 1024
#define O_ 6
#define E_ 128
#define KS_ 16            // k-split for u-sum partials
#define KT_ 32            // k tile per block in the fused pass
#define NBLK_K (K_/KT_)   // 32 k-tiles
#define DSP_ 256          // d-splits per o in k_v_part
#define DPB_ (D_/DSP_)    // 4 d per block
#define WDT_ 16           // d rows per k_w block

// ---------------- scratch (device globals; no allocation allowed) ----------------
__device__ __align__(16) float g_us_part[B_*KS_*D_];
__device__ __align__(16) float g_w[B_*O_*D_];          // w[b,o,d] = sum_e W[o,d,e]*v[b,o,e]
__device__ __align__(16) float g_logits[B_*K_*O_];     // logits after iteration-2
__device__ __align__(16) float g_t_part[(size_t)B_*NBLK_K*O_*D_];   // 6.3MB
__device__ __align__(16) float g_vpart[O_][DSP_][B_][E_];           // 6.3MB
__device__ __align__(16) float g_v[B_*O_*E_];          // current squashed v
__device__ unsigned char g_mask[B_*K_];

// ---------------- u-sum over k (deterministic split-K) + fused mask ingest ------
__global__ void k_usum_part(const float* __restrict__ u, const void* __restrict__ raw) {
    int tid = threadIdx.x;                    // 256
    int d = blockIdx.x * 256 + tid;
    int ks = blockIdx.y;
    int b = blockIdx.z;
    // fused mask ingest: 8 blocks (x==0, ks==0), one per b, each handles its slice.
    if (blockIdx.x == 0 && ks == 0) {
        __shared__ int flag;
        if (tid == 0) flag = 0;
        __syncthreads();
        const unsigned int* w32 = (const unsigned int*)raw;
        int f = 0;
        for (int i = tid; i < (B_*K_)/4; i += 256)
            if (w32[i] > 1u) f = 1;          // packed bytes => value like 0x00010001
        if (f) atomicOr(&flag, 1);
        __syncthreads();
        int isbyte = flag;
        const unsigned char* b8 = (const unsigned char*)raw;
        for (int i = tid; i < K_; i += 256) {
            int idx = b*K_ + i;
            unsigned char m = isbyte ? b8[idx] : (unsigned char)(w32[idx] != 0u);
            g_mask[idx] = m ? (unsigned char)1 : (unsigned char)0;
        }
    }
    int k0 = ks * (K_/KS_);
    const float* up = u + ((size_t)b*K_ + k0)*D_ + d;
    float s = 0.f;
    #pragma unroll 8
    for (int k = 0; k < K_/KS_; ++k) s += up[(size_t)k*D_];
    g_us_part[((size_t)b*KS_ + ks)*D_ + d] = s;
}

// ---------------- v partials (t-reduction fused, 4-thread-split) ----------------
// vpart[o,dblk,b,e] = sum_{d in blk} t[b,o,d]*W[o,d,e]
// t[b,o,d] = sum over NBLK_K g_t_part (use_t=1) or sum over KS_ g_us_part (use_t=0).
__global__ void __launch_bounds__(128) k_v_part(int use_t, const float* __restrict__ W) {
    int o = blockIdx.y;
    int dblk = blockIdx.x;            // [0, DSP_)
    int d0 = dblk * DPB_;
    int tid = threadIdx.x;            // 128
    __shared__ float red[B_*DPB_][4];
    __shared__ float st[B_][DPB_];
    {
        int entry = tid >> 2;         // 0..31 = b*DPB_+dd
        int sub = tid & 3;
        int b = entry / DPB_, dd = entry % DPB_;
        float s = 0.f;
        if (use_t) {
            const float* p = g_t_part + ((size_t)b*NBLK_K*O_ + o)*D_ + d0 + dd;
            #pragma unroll 8
            for (int j = sub; j < NBLK_K; j += 4) s += p[(size_t)j*O_*D_];
        } else {
            const float* p = g_us_part + (size_t)b*KS_*D_ + d0 + dd;
            #pragma unroll 4
            for (int j = sub; j < KS_; j += 4) s += p[(size_t)j*D_];
        }
        red[entry][sub] = s;
    }
    __syncthreads();
    if (tid < B_*DPB_) {
        int b = tid / DPB_, dd = tid % DPB_;
        st[b][dd] = red[tid][0] + red[tid][1] + red[tid][2] + red[tid][3];
    }
    __syncthreads();
    int e = tid;
    const float* Wo = W + ((size_t)o*D_ + d0)*E_ + e;
    float acc[B_];
    #pragma unroll
    for (int b = 0; b < B_; ++b) acc[b] = 0.f;
    #pragma unroll
    for (int dd = 0; dd < DPB_; ++dd) {
        float wv = Wo[(size_t)dd*E_];
        #pragma unroll
        for (int b = 0; b < B_; ++b) acc[b] += wv * st[b][dd];
    }
    #pragma unroll
    for (int b = 0; b < B_; ++b) g_vpart[o][dblk][b][e] = acc[b];
}

// ---------------- combine partials + squash -> g_v (512 thr, 4-way e-split) -----
__global__ void __launch_bounds__(512) k_v_comb(float scale) {
    int bo = blockIdx.x;              // [0, B*O)
    int b = bo / O_;
    int o = bo % O_;
    int tid = threadIdx.x;            // 512
    int e = tid & (E_-1);
    int q = tid >> 7;                 // 0..3
    float v = 0.f;
    #pragma unroll 16
    for (int s = q; s < DSP_; s += 4) v += g_vpart[o][s][b][e];
    __shared__ float part[4][E_];
    __shared__ float sv[E_];
    __shared__ float ssq;
    part[q][e] = v;
    __syncthreads();
    if (q == 0) {
        v = (part[0][e] + part[1][e] + part[2][e] + part[3][e]) * scale;
        sv[e] = v;
    }
    __syncthreads();
    if (tid < 32) {
        float s2 = sv[tid]*sv[tid] + sv[tid+32]*sv[tid+32]
                 + sv[tid+64]*sv[tid+64] + sv[tid+96]*sv[tid+96];
        #pragma unroll
        for (int off = 16; off; off >>= 1) s2 += __shfl_xor_sync(0xffffffffu, s2, off);
        if (tid == 0) ssq = s2;
    }
    __syncthreads();
    if (q == 0) {
        float sq = ssq;
        float factor = sq / (1.f + sq) / (sqrtf(sq) + 1e-8f);
        g_v[(size_t)bo*E_ + e] = sv[e] * factor;
    }
}

// ---------------- w[b,o,d] = sum_e W[o,d,e] * v[b,o,e]  (shfl-free smem) --------
// Grid (D/WDT, O), 128 threads. Thread (dd,b) computes one length-128 dot
// entirely from padded shared memory: no shuffles, no bank conflicts.
__global__ void __launch_bounds__(128) k_w(const float* __restrict__ W) {
    int o = blockIdx.y;
    int d0 = blockIdx.x * WDT_;
    int tid = threadIdx.x;            // 128
    __shared__ float sw[WDT_][E_+1];  // padded: bank = (dd*129+e)%32
    __shared__ float sv[B_][E_+1];    // padded: bank = (b*129+e)%32
    // load W tile coalesced: 16 rows x 128
    const float* Wt = W + ((size_t)o*D_ + d0)*E_;
    #pragma unroll
    for (int r = 0; r < WDT_; ++r)
        sw[r][tid] = Wt[(size_t)r*E_ + tid];
    // load v for all batches of this o
    for (int i = tid; i < B_*E_; i += 128) {
        int b = i >> 7; int e = i & (E_-1);
        sv[b][e] = g_v[((size_t)b*O_ + o)*E_ + e];
    }
    __syncthreads();
    int dd = tid >> 3;                // 0..15
    int b  = tid & 7;                 // 0..7
    float a = 0.f;
    #pragma unroll 16
    for (int e = 0; e < E_; ++e)
        a += sw[dd][e] * sv[b][e];
    g_w[((size_t)b*O_ + o)*D_ + d0 + dd] = a;
}

// ---------------- fused routing pass (KT=32) ----------------
// iter3==0: logits2 -> g_logits.  iter3==1: probs3 broadcast directly to outp.
__global__ void k_pass(const float* __restrict__ u, int iter3,
                       float4* __restrict__ outp) {
    __shared__ float sh_w[O_*D_];                 // 24KB
    __shared__ __align__(16) float sh_p[KT_][O_]; // 192 floats = 48 float4
    int b = blockIdx.y;
    int kblk = blockIdx.x;
    int k0 = kblk * KT_;
    int tid = threadIdx.x;            // 256
    const float* wb = g_w + (size_t)b*O_*D_;
    for (int i = tid; i < O_*D_; i += 256) sh_w[i] = wb[i];
    __syncthreads();
    int warp = tid >> 5, lane = tid & 31;
    for (int kk = warp; kk < KT_; kk += 8) {
        int k = k0 + kk;
        const float* ur = u + ((size_t)b*K_ + k)*D_;
        float a0=0,a1=0,a2=0,a3=0,a4=0,a5=0;
        #pragma unroll
        for (int j = 0; j < D_/32; ++j) {
            int d = j*32 + lane;
            float uv = ur[d];
            a0 += uv * sh_w[0*D_+d];
            a1 += uv * sh_w[1*D_+d];
            a2 += uv * sh_w[2*D_+d];
            a3 += uv * sh_w[3*D_+d];
            a4 += uv * sh_w[4*D_+d];
            a5 += uv * sh_w[5*D_+d];
        }
        #pragma unroll
        for (int off = 16; off; off >>= 1) {
            a0 += __shfl_xor_sync(0xffffffffu, a0, off);
            a1 += __shfl_xor_sync(0xffffffffu, a1, off);
            a2 += __shfl_xor_sync(0xffffffffu, a2, off);
            a3 += __shfl_xor_sync(0xffffffffu, a3, off);
            a4 += __shfl_xor_sync(0xffffffffu, a4, off);
            a5 += __shfl_xor_sync(0xffffffffu, a5, off);
        }
        int base = (b*K_ + k)*O_;
        if (iter3) {
            a0 += g_logits[base+0]; a1 += g_logits[base+1];
            a2 += g_logits[base+2]; a3 += g_logits[base+3];
            a4 += g_logits[base+4]; a5 += g_logits[base+5];
        } else if (lane < O_) {
            float sv = a0;
            if (lane==1) sv=a1; else if (lane==2) sv=a2; else if (lane==3) sv=a3;
            else if (lane==4) sv=a4; else if (lane==5) sv=a5;
            g_logits[base+lane] = sv;
        }
        float m = fmaxf(fmaxf(fmaxf(a0,a1),fmaxf(a2,a3)),fmaxf(a4,a5));
        float e0=__expf(a0-m), e1=__expf(a1-m), e2=__expf(a2-m),
              e3=__expf(a3-m), e4=__expf(a4-m), e5=__expf(a5-m);
        float s = e0+e1+e2+e3+e4+e5;
        bool msk = (g_mask[b*K_ + k] != 0);
        float inv = msk ? (1.0f/6.0f) : (1.0f/s);
        float p0 = msk?inv:e0*inv, p1 = msk?inv:e1*inv, p2 = msk?inv:e2*inv;
        float p3 = msk?inv:e3*inv, p4 = msk?inv:e4*inv, p5 = msk?inv:e5*inv;
        if (lane < O_) {
            float pv = p0;
            if (lane==1) pv=p1; else if (lane==2) pv=p2; else if (lane==3) pv=p3;
            else if (lane==4) pv=p4; else if (lane==5) pv=p5;
            sh_p[kk][lane] = pv;
        }
    }
    __syncthreads();
    // phase B: partial t[o,d] = sum_{k in tile} p[k,o] * u[b,k,d]
    float* tp = g_t_part + ((size_t)b*NBLK_K + kblk)*O_*D_;
    const float* ub = u + ((size_t)b*K_ + k0)*D_;
    #pragma unroll
    for (int r = 0; r < D_/256; ++r) {
        int d = tid + 256*r;
        float t0=0,t1=0,t2=0,t3=0,t4=0,t5=0;
        #pragma unroll 8
        for (int kk = 0; kk < KT_; ++kk) {
            float uv = ub[(size_t)kk*D_ + d];   // hot in L1/L2 from phase A
            t0 += uv*sh_p[kk][0]; t1 += uv*sh_p[kk][1]; t2 += uv*sh_p[kk][2];
            t3 += uv*sh_p[kk][3]; t4 += uv*sh_p[kk][4]; t5 += uv*sh_p[kk][5];
        }
        tp[0*D_+d]=t0; tp[1*D_+d]=t1; tp[2*D_+d]=t2;
        tp[3*D_+d]=t3; tp[4*D_+d]=t4; tp[5*D_+d]=t5;
    }
    // phase C (iter3 only): broadcast this tile's probs to all L rows of output.
    if (iter3) {
        const float4* sp4 = (const float4*)&sh_p[0][0];   // 48 float4
        const int NV = KT_*O_/4;                           // 48
        size_t dstbase = (size_t)b*L_*(K_*O_/4) + (size_t)kblk*NV;
        for (int idx = tid; idx < L_*NV; idx += 256) {
            int l = idx / NV;
            int j = idx - l*NV;
            __stcs(outp + dstbase + (size_t)l*(K_*O_/4) + j, sp4[j]);
        }
    }
}

// ---------------- outputs_v broadcast ----------------
__global__ void k_bcast_v(float4* __restrict__ dst) {
    const float4* src = (const float4*)g_v;
    const int per = O_*E_/4;                   // 192
    const int total = B_*L_*per;
    for (int i = blockIdx.x*blockDim.x + threadIdx.x; i < total;
         i += gridDim.x*blockDim.x) {
        int bl = i / per;
        int j = i - bl*per;
        int b = bl >> 10;
        __stcs(dst + i, src[b*per + j]);
    }
}

// ---------------- launch ----------------
extern "C" void kernel_launch(void* const* d_in, const int* in_sizes, int n_in,
                              void* d_out, int out_size) {
    const float* u    = (const float*)d_in[0];   // inputs_u (B,K,D)
    // d_in[1] = context_sequence — unused by the math (shape only)
    const float* W    = (const float*)d_in[2];   // route_weights (O,D,E)
    const void*  mask = d_in[3];                 // inputs_mask (B,K)

    float* out   = (float*)d_out;
    float4* outv = (float4*)out;                                  // outputs_v (B,L,O,E)
    float4* outp = (float4*)(out + (size_t)B_*L_*O_*E_);          // probs_c   (B,L,K,O)

    // u-sum partials + mask ingest (fused)
    k_usum_part<<<dim3(D_/256, KS_, B_), 256>>>(u, mask);

    // iteration 1: v1 = squash((1/6) * usum @ W); w1 = W @ v1
    k_v_part<<<dim3(DSP_, O_), 128>>>(0, W);
    k_v_comb<<<B_*O_, 512>>>(1.0f/6.0f);
    k_w<<<dim3(D_/WDT_, O_), 128>>>(W);

    // iteration 2: logits2 = u.w1 (store), probs2, t2 -> v2 -> w2
    k_pass<<<dim3(NBLK_K, B_), 256>>>(u, 0, outp);
    k_v_part<<<dim3(DSP_, O_), 128>>>(1, W);
    k_v_comb<<<B_*O_, 512>>>(1.0f);
    k_w<<<dim3(D_/WDT_, O_), 128>>>(W);

    // iteration 3: logits3 = logits2 + u.w2, probs3 broadcast to outp, t3 -> v3
    k_pass<<<dim3(NBLK_K, B_), 256>>>(u, 1, outp);
    k_v_part<<<dim3(DSP_, O_), 128>>>(1, W);
    k_v_comb<<<B_*O_, 512>>>(1.0f);

    // broadcast outputs_v over L
    k_bcast_v<<<1024, 256>>>(outv);
}